// round 6
// baseline (speedup 1.0000x reference)
#include <cuda_runtime.h>
#include <cuda_bf16.h>

#define Bb   16
#define Nn   8
#define Tt   65536
#define CPB  32            // chunks per batch
#define TPB  128
#define NVALS 80           // 64 gram + 8 sum(x^2) + 8 sum(y^2)
#define ITERS ((Tt / CPB) / 4 / TPB)   // = 4 float4 iterations per thread
#define GRID (Bb * CPB)

// Partial sums laid out [batch][value][chunk] so k_sink reduces over a
// contiguous 128B line per output. No atomics anywhere -> deterministic.
__device__ float g_partial[Bb * NVALS * CPB];

typedef unsigned long long u64;

__device__ __forceinline__ u64 pack2(float lo, float hi) {
    u64 r;
    asm("mov.b64 %0, {%1, %2};" : "=l"(r) : "f"(lo), "f"(hi));
    return r;
}
__device__ __forceinline__ void unpack2(u64 v, float& lo, float& hi) {
    asm("mov.b64 {%0, %1}, %2;" : "=f"(lo), "=f"(hi) : "l"(v));
}
// d = a*b + d, packed fp32x2 (Blackwell FFMA2; PTX-only form).
__device__ __forceinline__ void ffma2(u64& d, u64 a, u64 b) {
    asm("fma.rn.f32x2 %0, %1, %2, %0;" : "+l"(d) : "l"(a), "l"(b));
}
__device__ __forceinline__ float f4c(float4 v, int t) {
    return t == 0 ? v.x : t == 1 ? v.y : t == 2 ? v.z : v.w;
}

// ---------------------------------------------------------------------------
// Kernel 1: streaming Gram + self-norms, FFMA2 (f32x2) j-packed.
// Each 64-bit accumulator holds (G[i][2jp], G[i][2jp+1]) — one FFMA2 retires
// two FMAs, halving FP32-pipe issue (320 -> 176 ops/iter) while each packed
// lane remains a bit-exact independent scalar sum. MLP=16 loads per iter.
// Acc regs: 64 cross + 16 sx + 8 sy = 88; peak live ~160 < 170 (lb 128,3).
// ---------------------------------------------------------------------------
__global__ __launch_bounds__(TPB, 3) void k_gram(const float* __restrict__ inp,
                                                 const float* __restrict__ tgt) {
    const int b   = blockIdx.x / CPB;
    const int c   = blockIdx.x % CPB;
    const int tid = threadIdx.x;

    const float4* ip = reinterpret_cast<const float4*>(inp) + (size_t)b * Nn * (Tt / 4);
    const float4* tp = reinterpret_cast<const float4*>(tgt) + (size_t)b * Nn * (Tt / 4);
    const int base = c * (Tt / CPB / 4) + tid;

    u64 cr2[Nn][4];          // (G[i][2jp], G[i][2jp+1])
    u64 sx2[Nn];             // (sum x_i^2, dup)
    u64 sy2[4];              // (sum y_{2jp}^2, sum y_{2jp+1}^2)
#pragma unroll
    for (int i = 0; i < Nn; i++) {
        sx2[i] = 0ull;
#pragma unroll
        for (int jp = 0; jp < 4; jp++) cr2[i][jp] = 0ull;
    }
#pragma unroll
    for (int jp = 0; jp < 4; jp++) sy2[jp] = 0ull;

#pragma unroll
    for (int k = 0; k < ITERS; k++) {
        const int idx = base + k * TPB;
        float4 av[Nn], bv[Nn];
#pragma unroll
        for (int i = 0; i < Nn; i++) av[i] = ip[i * (Tt / 4) + idx];
#pragma unroll
        for (int j = 0; j < Nn; j++) bv[j] = tp[j * (Tt / 4) + idx];

#pragma unroll
        for (int t = 0; t < 4; t++) {
            u64 yy[4];
#pragma unroll
            for (int jp = 0; jp < 4; jp++) {
                yy[jp] = pack2(f4c(bv[2 * jp], t), f4c(bv[2 * jp + 1], t));
                ffma2(sy2[jp], yy[jp], yy[jp]);
            }
#pragma unroll
            for (int i = 0; i < Nn; i++) {
                const float xv = f4c(av[i], t);
                const u64 xx = pack2(xv, xv);
                ffma2(sx2[i], xx, xx);
#pragma unroll
                for (int jp = 0; jp < 4; jp++)
                    ffma2(cr2[i][jp], xx, yy[jp]);
            }
        }
    }

    // Unpack to the scalar NVALS layout, then fixed-order reduction.
    float acc[NVALS];
#pragma unroll
    for (int i = 0; i < Nn; i++) {
#pragma unroll
        for (int jp = 0; jp < 4; jp++)
            unpack2(cr2[i][jp], acc[i * 8 + 2 * jp], acc[i * 8 + 2 * jp + 1]);
        float lo, hi;
        unpack2(sx2[i], lo, hi);
        acc[64 + i] = lo;
    }
#pragma unroll
    for (int jp = 0; jp < 4; jp++)
        unpack2(sy2[jp], acc[72 + 2 * jp], acc[72 + 2 * jp + 1]);

    __shared__ float sm[TPB / 32][NVALS];
    const int lane = tid & 31, warp = tid >> 5;
#pragma unroll
    for (int v = 0; v < NVALS; v++) {
        float x = acc[v];
#pragma unroll
        for (int off = 16; off; off >>= 1) x += __shfl_down_sync(0xffffffffu, x, off);
        if (lane == 0) sm[warp][v] = x;
    }
    __syncthreads();
    if (tid < NVALS) {
        float s = 0.f;
#pragma unroll
        for (int w = 0; w < TPB / 32; w++) s += sm[w][tid];
        g_partial[(b * NVALS + tid) * CPB + c] = s;   // [b][val][chunk]
    }
}

// ---------------------------------------------------------------------------
// Kernel 2: unchanged from R5 (512 threads; contiguous Phase-A reduction;
// one warp per batch; linear-domain shuffle Sinkhorn).
// ---------------------------------------------------------------------------
__global__ __launch_bounds__(512) void k_sink(float* __restrict__ out, int out_size) {
    __shared__ float G[Bb][NVALS];
    __shared__ float bloss[Bb];

    const int tid = threadIdx.x;

    for (int v = tid; v < Bb * NVALS; v += 512) {
        const float4* p = reinterpret_cast<const float4*>(&g_partial[v * CPB]);
        float s = 0.f;
#pragma unroll
        for (int q = 0; q < CPB / 4; q++) {
            const float4 x = p[q];
            s += x.x + x.y + x.z + x.w;
        }
        G[v / NVALS][v % NVALS] = s;
    }
    __syncthreads();

    const int w  = tid >> 5;
    const int l  = tid & 31;
    const int j  = l & 7;
    const int i0 = l >> 3;
    const int i1 = i0 + 4;
    const float invT = 1.0f / (float)Tt;

    if (w < Bb) {
        const float L0 = (G[w][64 + i0] + G[w][72 + j] - 2.f * G[w][i0 * 8 + j]) * invT;
        const float L1 = (G[w][64 + i1] + G[w][72 + j] - 2.f * G[w][i1 * 8 + j]) * invT;
        float p0 = __expf(-L0), p1 = __expf(-L1);

#pragma unroll
        for (int it = 0; it < 10; it++) {
            float s = p0 + p1;
            s += __shfl_xor_sync(0xffffffffu, s, 8);
            s += __shfl_xor_sync(0xffffffffu, s, 16);
            const float r = __fdividef(1.f, s);
            p0 *= r;
            p1 *= r;

            float s0 = p0, s1 = p1;
            s0 += __shfl_xor_sync(0xffffffffu, s0, 1);
            s1 += __shfl_xor_sync(0xffffffffu, s1, 1);
            s0 += __shfl_xor_sync(0xffffffffu, s0, 2);
            s1 += __shfl_xor_sync(0xffffffffu, s1, 2);
            s0 += __shfl_xor_sync(0xffffffffu, s0, 4);
            s1 += __shfl_xor_sync(0xffffffffu, s1, 4);
            p0 *= __fdividef(1.f, s0);
            p1 *= __fdividef(1.f, s1);
        }

        float lp = (L0 + __logf(p0)) * p0 + (L1 + __logf(p1)) * p1;
#pragma unroll
        for (int off = 16; off; off >>= 1) lp += __shfl_xor_sync(0xffffffffu, lp, off);
        if (l == 0) bloss[w] = lp;

        float v0 = p0, v1 = p1;
        int   a0 = j,  a1 = j;
#pragma unroll
        for (int off = 1; off <= 4; off <<= 1) {
            float ov = __shfl_xor_sync(0xffffffffu, v0, off);
            int   oa = __shfl_xor_sync(0xffffffffu, a0, off);
            if (ov > v0 || (ov == v0 && oa < a0)) { v0 = ov; a0 = oa; }
            ov = __shfl_xor_sync(0xffffffffu, v1, off);
            oa = __shfl_xor_sync(0xffffffffu, a1, off);
            if (ov > v1 || (ov == v1 && oa < a1)) { v1 = ov; a1 = oa; }
        }
        if (out_size >= 1 + Bb * Nn && j == 0) {
            out[1 + w * Nn + i0] = (float)a0;
            out[1 + w * Nn + i1] = (float)a1;
        }
    }

    __syncthreads();
    if (tid == 0) {
        float s = 0.f;
#pragma unroll
        for (int b = 0; b < Bb; b++) s += bloss[b];
        out[0] = s * (1.0f / (float)Bb);
    }
}

// ---------------------------------------------------------------------------
extern "C" void kernel_launch(void* const* d_in, const int* in_sizes, int n_in,
                              void* d_out, int out_size) {
    const float* inp = (const float*)d_in[0];
    const float* tgt = (const float*)d_in[1];
    k_gram<<<GRID, TPB>>>(inp, tgt);
    k_sink<<<1, 512>>>((float*)d_out, out_size);
}